// round 13
// baseline (speedup 1.0000x reference)
#include <cuda_runtime.h>
#include <math_constants.h>

// Problem constants (fixed shape)
#define BB 8
#define SS 512
#define ROWS (BB * SS)
#define VV 32000
#define V4 (VV / 4)            // 8000 float4 per row
#define EPS_SMOOTH 0.1f
#define REP_W 0.2f
#define IGNORE_IDX (-100)

#define RK_THREADS 512
#define FULL_IT (V4 / RK_THREADS)       // 15
#define REM (V4 - FULL_IT * RK_THREADS) // 320

#define GRID 296                         // 2 blocks/SM x 148 SMs, all resident
#define SLICES 8
#define RB_BLOCKS (BB * SLICES)          // 64
#define ILOC (SS / SLICES)               // 64
#define JLEN (SS / 8)                    // 64

// Scratch (no allocation allowed -> __device__ globals; zero-init; counters
// reset by the final block each replay)
__device__ float g_per_tok[ROWS];
__device__ float g_valid[ROWS];
__device__ int   g_pred[ROWS];
__device__ float g_ent_part[RB_BLOCKS];
__device__ float g_nu_part[RB_BLOCKS];
__device__ float g_pt_part[RB_BLOCKS];
__device__ float g_v_part[RB_BLOCKS];
__device__ float g_tot_b[BB];
__device__ int   g_ticket;
__device__ int   g_arrive;
__device__ int   g_arrive2;

// ---------------- packed f32x2 helpers (Blackwell) ----------------
__device__ __forceinline__ unsigned long long pack2(float a, float b) {
    unsigned long long r;
    asm("mov.b64 %0, {%1, %2};" : "=l"(r) : "f"(a), "f"(b));
    return r;
}
__device__ __forceinline__ void unpack2(unsigned long long p, float& a, float& b) {
    asm("mov.b64 {%0, %1}, %2;" : "=f"(a), "=f"(b) : "l"(p));
}
__device__ __forceinline__ unsigned long long addf2(unsigned long long a, unsigned long long b) {
    unsigned long long r;
    asm("add.rn.f32x2 %0, %1, %2;" : "=l"(r) : "l"(a), "l"(b));
    return r;
}
__device__ __forceinline__ unsigned long long mulf2(unsigned long long a, unsigned long long b) {
    unsigned long long r;
    asm("mul.rn.f32x2 %0, %1, %2;" : "=l"(r) : "l"(a), "l"(b));
    return r;
}
__device__ __forceinline__ float ex2f(float x) {
    float r;
    asm("ex2.approx.f32 %0, %1;" : "=f"(r) : "f"(x));
    return r;
}
__device__ __forceinline__ int ld_acquire(int* p) {
    int v;
    asm volatile("ld.global.acquire.gpu.b32 %0, [%1];" : "=r"(v) : "l"(p));
    return v;
}

// ---------------------------------------------------------------------------
// Persistent fused kernel with DYNAMIC row ticketing.
// Static persistent striding made phase A run at the SLOWEST SM's pace
// (far-die L2, queue contention) and the grid barrier amplified it; a ticket
// counter load-balances like the HW scheduler does for many small blocks,
// while keeping the zero-tail fused structure. Next ticket is fetched during
// the current row's stream, hiding the ATOMG latency.
// ---------------------------------------------------------------------------
__global__ void __launch_bounds__(RK_THREADS, 2)
fused_kernel(const float* __restrict__ logits, const void* __restrict__ labels,
             float* __restrict__ out, int out_size) {
    const int tid = threadIdx.x;
    const int bid = blockIdx.x;

    __shared__ float shs[2][16], sht[2][16], shm[2][16];
    __shared__ int   sha[2][16];
    __shared__ int   sh_row;

    // label width detect: warp 0 only, result in registers
    int is64 = 0;
    if (tid < 32) {
        const int* lw = (const int*)labels;
        bool ok = true;
        #pragma unroll
        for (int kq = 0; kq < 8; kq++) {
            int pi = tid + kq * 32;
            int lo = __ldg(&lw[2 * pi]);
            int hi = __ldg(&lw[2 * pi + 1]);
            if (hi != (lo < 0 ? -1 : 0)) ok = false;
        }
        unsigned ball = __ballot_sync(0xffffffffu, ok);
        is64 = (ball == 0xffffffffu) ? 1 : 0;
    }

    const unsigned long long L2E2 = pack2(1.4426950408889634f, 1.4426950408889634f);

    // ---------------- Phase A: dynamically ticketed rows ----------------
    int next_row = 0;
    if (tid == 0) next_row = atomicAdd(&g_ticket, 1);

    int par = 0;
    while (true) {
        if (tid == 0) sh_row = next_row;
        __syncthreads();
        const int row = sh_row;
        if (row >= ROWS) break;

        // fetch NEXT ticket now; ~320cyc ATOMG hides under this row's stream
        if (tid == 0) next_row = atomicAdd(&g_ticket, 1);

        const float* __restrict__ x = logits + (size_t)row * VV;
        const float4* __restrict__ x4 = (const float4*)x;

        // prefetch label -> x[label] (resolves during the row stream)
        long long lab = 0;
        float xl = 0.f;
        if (tid == 0) {
            if (is64) lab = ((const long long*)labels)[row];
            else      lab = (long long)(((const int*)labels)[row]);
            int li = (lab != IGNORE_IDX) ? (int)lab : 0;
            xl = __ldg(&x[li]);
        }

        unsigned long long s01 = 0ull, s23 = 0ull;
        unsigned long long t01 = 0ull, t23 = 0ull;
        float k0 = -CUDART_INF_F, k1 = -CUDART_INF_F, k2 = -CUDART_INF_F, k3 = -CUDART_INF_F;

        #define BODY(kk, i)                                                         \
            do {                                                                    \
                float4 v = x4[(i)];                                                 \
                unsigned long long vxy = pack2(v.x, v.y);                           \
                unsigned long long vzw = pack2(v.z, v.w);                           \
                t01 = addf2(t01, vxy);                                              \
                t23 = addf2(t23, vzw);                                              \
                unsigned long long wxy = mulf2(vxy, L2E2);                          \
                unsigned long long wzw = mulf2(vzw, L2E2);                          \
                float w0, w1, w2, w3;                                               \
                unpack2(wxy, w0, w1);                                               \
                unpack2(wzw, w2, w3);                                               \
                float e0 = ex2f(w0), e1 = ex2f(w1), e2 = ex2f(w2), e3 = ex2f(w3);   \
                s01 = addf2(s01, pack2(e0, e1));                                    \
                s23 = addf2(s23, pack2(e2, e3));                                    \
                k0 = fmaxf(k0, __int_as_float((__float_as_int(v.x) & ~15) | (kk))); \
                k1 = fmaxf(k1, __int_as_float((__float_as_int(v.y) & ~15) | (kk))); \
                k2 = fmaxf(k2, __int_as_float((__float_as_int(v.z) & ~15) | (kk))); \
                k3 = fmaxf(k3, __int_as_float((__float_as_int(v.w) & ~15) | (kk))); \
            } while (0)

        #pragma unroll 5
        for (int k = 0; k < FULL_IT; k++) {
            BODY(k, tid + k * RK_THREADS);
        }
        if (tid < REM) {
            BODY(FULL_IT, tid + FULL_IT * RK_THREADS);
        }
        #undef BODY

        float sa, sb, sc, sd, ta, tb, tc, td;
        unpack2(s01, sa, sb);
        unpack2(s23, sc, sd);
        unpack2(t01, ta, tb);
        unpack2(t23, tc, td);
        float s = (sa + sb) + (sc + sd);
        float t = (ta + tb) + (tc + td);

        float bk = k0;
        int bs = 0;
        if (k1 > bk) { bk = k1; bs = 1; }
        if (k2 > bk) { bk = k2; bs = 2; }
        if (k3 > bk) { bk = k3; bs = 3; }
        int kb = __float_as_int(bk);
        int iter = kb & 15;
        float m = __int_as_float(kb & ~15);
        int am = (((iter * RK_THREADS) + tid) << 2) + bs;

        #pragma unroll
        for (int off = 16; off; off >>= 1) {
            float s2r = __shfl_down_sync(0xffffffffu, s, off);
            float t2r = __shfl_down_sync(0xffffffffu, t, off);
            float m2r = __shfl_down_sync(0xffffffffu, m, off);
            int   a2r = __shfl_down_sync(0xffffffffu, am, off);
            s += s2r;
            t += t2r;
            if (m2r > m || (m2r == m && a2r < am)) am = a2r;
            m = fmaxf(m, m2r);
        }

        int wid = tid >> 5;
        if ((tid & 31) == 0) { shs[par][wid] = s; sht[par][wid] = t; shm[par][wid] = m; sha[par][wid] = am; }
        __syncthreads();
        // parity scratch is further protected by the ticket barrier at loop top

        if (tid < 32) {
            float es = 0.f, et = 0.f, em = -CUDART_INF_F;
            int   ea = 0x7fffffff;
            if (tid < 16) { es = shs[par][tid]; et = sht[par][tid]; em = shm[par][tid]; ea = sha[par][tid]; }
            #pragma unroll
            for (int off = 8; off; off >>= 1) {
                float s2r = __shfl_down_sync(0xffffffffu, es, off);
                float t2r = __shfl_down_sync(0xffffffffu, et, off);
                float m2r = __shfl_down_sync(0xffffffffu, em, off);
                int   a2r = __shfl_down_sync(0xffffffffu, ea, off);
                es += s2r;
                et += t2r;
                if (m2r > em || (m2r == em && a2r < ea)) ea = a2r;
                em = fmaxf(em, m2r);
            }
            if (tid == 0) {
                float lse = logf(es);
                bool valid = (lab != IGNORE_IDX);
                float per = lse - (1.0f - EPS_SMOOTH) * xl - EPS_SMOOTH * (et / (float)VV);
                g_per_tok[row] = valid ? per : 0.f;
                g_valid[row]   = valid ? 1.f : 0.f;
                g_pred[row]    = ea;
            }
        }
        par ^= 1;
    }

    // ---------------- grid barrier ----------------
    __threadfence();
    __syncthreads();
    if (tid == 0) atomicAdd(&g_arrive, 1);

    if (bid >= RB_BLOCKS) return;

    if (tid == 0) {
        while (ld_acquire(&g_arrive) < GRID) __nanosleep(64);
    }
    __syncthreads();
    __threadfence();

    // ---------------- Phase B: rep loss ----------------
    const int b  = bid >> 3;
    const int sl = bid & 7;
    const int il = tid >> 3;
    const int ch = tid & 7;
    const int i  = sl * ILOC + il;

    __shared__ int   sp[SS];
    __shared__ float sv[SS];
    __shared__ float red1[16], red2[16], red3[16], red4[16];

    {
        int row = b * SS + tid;
        sp[tid] = g_pred[row];
        sv[tid] = g_valid[row];
    }
    __syncthreads();

    float total = sv[tid];
    #pragma unroll
    for (int off = 16; off; off >>= 1) total += __shfl_down_sync(0xffffffffu, total, off);
    if ((tid & 31) == 0) red1[tid >> 5] = total;
    __syncthreads();
    if (tid < 16) {
        float xx = red1[tid];
        #pragma unroll
        for (int off = 8; off; off >>= 1) xx += __shfl_down_sync(0xffffu, xx, off);
        if (tid == 0) red1[0] = xx;
    }
    __syncthreads();
    total = red1[0];
    __syncthreads();

    int   p  = sp[i];
    float vi = sv[i];
    float c = 0.f;
    int lt = 0;
    #pragma unroll 8
    for (int jj = 0; jj < JLEN; jj++) {
        int j = ch + (jj << 3);
        bool match = (sp[j] == p) && (sv[j] > 0.f);
        c += match ? 1.f : 0.f;
        lt |= (match && (j < i)) ? 1 : 0;
    }
    #pragma unroll
    for (int off = 1; off < 8; off <<= 1) {
        c  += __shfl_xor_sync(0xffffffffu, c,  off);
        lt |= __shfl_xor_sync(0xffffffffu, lt, off);
    }

    float ent = 0.f, nu = 0.f, pts = 0.f, vls = 0.f;
    if (ch == 0) {
        bool first = (vi > 0.f) && !lt;
        if (first) {
            float pr = c / fmaxf(total, 1.f);
            ent = -pr * logf(pr + 1e-10f);
            nu  = 1.f;
        }
        int row = b * SS + i;
        pts = g_per_tok[row];
        vls = vi;
    }

    #pragma unroll
    for (int off = 16; off; off >>= 1) {
        ent += __shfl_down_sync(0xffffffffu, ent, off);
        nu  += __shfl_down_sync(0xffffffffu, nu,  off);
        pts += __shfl_down_sync(0xffffffffu, pts, off);
        vls += __shfl_down_sync(0xffffffffu, vls, off);
    }
    if ((tid & 31) == 0) { red1[tid >> 5] = ent; red2[tid >> 5] = nu; red3[tid >> 5] = pts; red4[tid >> 5] = vls; }
    __syncthreads();
    if (tid < 16) {
        float e = red1[tid], n = red2[tid], q = red3[tid], w = red4[tid];
        #pragma unroll
        for (int off = 8; off; off >>= 1) {
            e += __shfl_down_sync(0xffffu, e, off);
            n += __shfl_down_sync(0xffffu, n, off);
            q += __shfl_down_sync(0xffffu, q, off);
            w += __shfl_down_sync(0xffffu, w, off);
        }
        if (tid == 0) {
            g_ent_part[bid] = e;
            g_nu_part[bid]  = n;
            g_pt_part[bid]  = q;
            g_v_part[bid]   = w;
            if (sl == 0) g_tot_b[b] = total;
        }
    }
    __syncthreads();

    if (tid == 0) {
        __threadfence();
        int old = atomicAdd(&g_arrive2, 1);
        if (old == RB_BLOCKS - 1) {
            __threadfence();
            float rep = 0.f;
            #pragma unroll
            for (int bb = 0; bb < BB; bb++) {
                float eb = 0.f, nb = 0.f;
                #pragma unroll
                for (int ss2 = 0; ss2 < SLICES; ss2++) {
                    eb += g_ent_part[bb * SLICES + ss2];
                    nb += g_nu_part[bb * SLICES + ss2];
                }
                float tb2 = g_tot_b[bb];
                rep += (tb2 > 0.f) ? (1.f - eb / logf(nb + 1.f)) : 0.f;
            }
            rep /= (float)BB;
            float cen = 0.f, ced = 0.f;
            #pragma unroll
            for (int jq = 0; jq < RB_BLOCKS; jq++) {
                cen += g_pt_part[jq];
                ced += g_v_part[jq];
            }
            float ce = cen / fmaxf(ced, 1.f);
            float tot = ce + REP_W * rep;
            out[0] = tot;
            if (out_size > 1) out[1] = ce;
            if (out_size > 2) out[2] = rep;
            g_ticket  = 0;   // replay-safe resets (all blocks already done)
            g_arrive  = 0;
            g_arrive2 = 0;
        }
    }
}

extern "C" void kernel_launch(void* const* d_in, const int* in_sizes, int n_in,
                              void* d_out, int out_size) {
    const float* logits = (const float*)d_in[0];
    const void*  labels = d_in[1];

    fused_kernel<<<GRID, RK_THREADS>>>(logits, labels, (float*)d_out, out_size);
}

// round 14
// speedup vs baseline: 1.0934x; 1.0934x over previous
#include <cuda_runtime.h>
#include <math_constants.h>

// Problem constants (fixed shape)
#define BB 8
#define SS 512
#define ROWS (BB * SS)
#define VV 32000
#define V4 (VV / 4)            // 8000 float4 per row
#define EPS_SMOOTH 0.1f
#define REP_W 0.2f
#define IGNORE_IDX (-100)

#define RK_THREADS 512
#define FULL_IT (V4 / RK_THREADS)       // 15
#define REM (V4 - FULL_IT * RK_THREADS) // 320

#define SLICES 8
#define RB_BLOCKS (BB * SLICES)          // 64 rep slices
#define REP_TICKET0 (ROWS - RB_BLOCKS)   // arrival tickets >= this do Phase B
#define ILOC (SS / SLICES)               // 64
#define JLEN (SS / 8)                    // 64

// Scratch (no allocation allowed -> __device__ globals; zero-init; counters
// reset by the final combine block each replay)
__device__ float g_per_tok[ROWS];
__device__ float g_valid[ROWS];
__device__ int   g_pred[ROWS];
__device__ float g_ent_part[RB_BLOCKS];
__device__ float g_nu_part[RB_BLOCKS];
__device__ float g_pt_part[RB_BLOCKS];
__device__ float g_v_part[RB_BLOCKS];
__device__ float g_tot_b[BB];
__device__ int   g_arrive;
__device__ int   g_arrive2;

// ---------------- packed f32x2 helpers (Blackwell) ----------------
__device__ __forceinline__ unsigned long long pack2(float a, float b) {
    unsigned long long r;
    asm("mov.b64 %0, {%1, %2};" : "=l"(r) : "f"(a), "f"(b));
    return r;
}
__device__ __forceinline__ void unpack2(unsigned long long p, float& a, float& b) {
    asm("mov.b64 {%0, %1}, %2;" : "=f"(a), "=f"(b) : "l"(p));
}
__device__ __forceinline__ unsigned long long addf2(unsigned long long a, unsigned long long b) {
    unsigned long long r;
    asm("add.rn.f32x2 %0, %1, %2;" : "=l"(r) : "l"(a), "l"(b));
    return r;
}
__device__ __forceinline__ unsigned long long mulf2(unsigned long long a, unsigned long long b) {
    unsigned long long r;
    asm("mul.rn.f32x2 %0, %1, %2;" : "=l"(r) : "l"(a), "l"(b));
    return r;
}
__device__ __forceinline__ float ex2f(float x) {
    float r;
    asm("ex2.approx.f32 %0, %1;" : "=f"(r) : "f"(x));
    return r;
}
__device__ __forceinline__ int ld_acquire(int* p) {
    int v;
    asm volatile("ld.global.acquire.gpu.b32 %0, [%1];" : "=r"(v) : "l"(p));
    return v;
}

// ---------------------------------------------------------------------------
// Single kernel, grid = 4096 (one block per row): the HW scheduler
// work-steals across ~14 waves (measured ~81us row phase in R4, vs ~95us for
// any persistent software schedule). Tail fused via arrival ticketing: the
// LAST 64 blocks to finish (tickets >= 4032) run the rep-loss slices and the
// 64th combines + writes out — zero extra kernel nodes (each measured to
// carry a 5-17us floor). Deadlock-free: spinners only exist when <=64 blocks
// remain unscheduled and >=232 SM slots are free.
// ---------------------------------------------------------------------------
__global__ void __launch_bounds__(RK_THREADS, 2)
fused_kernel(const float* __restrict__ logits, const void* __restrict__ labels,
             float* __restrict__ out, int out_size) {
    const int tid = threadIdx.x;
    const int row = blockIdx.x;

    __shared__ float shs[16], sht[16], shm[16];
    __shared__ int   sha[16];
    __shared__ int   sh_old;

    const float* __restrict__ x = logits + (size_t)row * VV;
    const float4* __restrict__ x4 = (const float4*)x;

    // label width detect at block TOP (warp 0): loads issue before/with the
    // row stream and resolve under it. (Trailing detect measured +10us in R6.)
    int is64 = 0;
    long long lab = 0;
    float xl = 0.f;
    if (tid < 32) {
        const int* lw = (const int*)labels;
        bool ok = true;
        #pragma unroll
        for (int kq = 0; kq < 8; kq++) {
            int pi = tid + kq * 32;
            int lo = __ldg(&lw[2 * pi]);
            int hi = __ldg(&lw[2 * pi + 1]);
            if (hi != (lo < 0 ? -1 : 0)) ok = false;
        }
        unsigned ball = __ballot_sync(0xffffffffu, ok);
        is64 = (ball == 0xffffffffu) ? 1 : 0;
        // prefetch label -> x[label]; resolves during the ~1.7us row stream
        if (tid == 0) {
            if (is64) lab = ((const long long*)labels)[row];
            else      lab = (long long)(((const int*)labels)[row]);
            int li = (lab != IGNORE_IDX) ? (int)lab : 0;
            xl = __ldg(&x[li]);
        }
    }

    const unsigned long long L2E2 = pack2(1.4426950408889634f, 1.4426950408889634f);

    unsigned long long s01 = 0ull, s23 = 0ull;
    unsigned long long t01 = 0ull, t23 = 0ull;
    float k0 = -CUDART_INF_F, k1 = -CUDART_INF_F, k2 = -CUDART_INF_F, k3 = -CUDART_INF_F;

    #define BODY(kk, i)                                                         \
        do {                                                                    \
            float4 v = x4[(i)];                                                 \
            unsigned long long vxy = pack2(v.x, v.y);                           \
            unsigned long long vzw = pack2(v.z, v.w);                           \
            t01 = addf2(t01, vxy);                                              \
            t23 = addf2(t23, vzw);                                              \
            unsigned long long wxy = mulf2(vxy, L2E2);                          \
            unsigned long long wzw = mulf2(vzw, L2E2);                          \
            float w0, w1, w2, w3;                                               \
            unpack2(wxy, w0, w1);                                               \
            unpack2(wzw, w2, w3);                                               \
            float e0 = ex2f(w0), e1 = ex2f(w1), e2 = ex2f(w2), e3 = ex2f(w3);   \
            s01 = addf2(s01, pack2(e0, e1));                                    \
            s23 = addf2(s23, pack2(e2, e3));                                    \
            k0 = fmaxf(k0, __int_as_float((__float_as_int(v.x) & ~15) | (kk))); \
            k1 = fmaxf(k1, __int_as_float((__float_as_int(v.y) & ~15) | (kk))); \
            k2 = fmaxf(k2, __int_as_float((__float_as_int(v.z) & ~15) | (kk))); \
            k3 = fmaxf(k3, __int_as_float((__float_as_int(v.w) & ~15) | (kk))); \
        } while (0)

    #pragma unroll 5
    for (int k = 0; k < FULL_IT; k++) {
        BODY(k, tid + k * RK_THREADS);
    }
    if (tid < REM) {
        BODY(FULL_IT, tid + FULL_IT * RK_THREADS);
    }
    #undef BODY

    float sa, sb, sc, sd, ta, tb, tc, td;
    unpack2(s01, sa, sb);
    unpack2(s23, sc, sd);
    unpack2(t01, ta, tb);
    unpack2(t23, tc, td);
    float s = (sa + sb) + (sc + sd);
    float t = (ta + tb) + (tc + td);

    float bk = k0;
    int bs = 0;
    if (k1 > bk) { bk = k1; bs = 1; }
    if (k2 > bk) { bk = k2; bs = 2; }
    if (k3 > bk) { bk = k3; bs = 3; }
    int kb = __float_as_int(bk);
    int iter = kb & 15;
    float m = __int_as_float(kb & ~15);
    int am = (((iter * RK_THREADS) + tid) << 2) + bs;

    #pragma unroll
    for (int off = 16; off; off >>= 1) {
        float s2r = __shfl_down_sync(0xffffffffu, s, off);
        float t2r = __shfl_down_sync(0xffffffffu, t, off);
        float m2r = __shfl_down_sync(0xffffffffu, m, off);
        int   a2r = __shfl_down_sync(0xffffffffu, am, off);
        s += s2r;
        t += t2r;
        if (m2r > m || (m2r == m && a2r < am)) am = a2r;
        m = fmaxf(m, m2r);
    }

    int wid = tid >> 5;
    if ((tid & 31) == 0) { shs[wid] = s; sht[wid] = t; shm[wid] = m; sha[wid] = am; }
    __syncthreads();

    if (tid < 32) {
        float es = 0.f, et = 0.f, em = -CUDART_INF_F;
        int   ea = 0x7fffffff;
        if (tid < 16) { es = shs[tid]; et = sht[tid]; em = shm[tid]; ea = sha[tid]; }
        #pragma unroll
        for (int off = 8; off; off >>= 1) {
            float s2r = __shfl_down_sync(0xffffffffu, es, off);
            float t2r = __shfl_down_sync(0xffffffffu, et, off);
            float m2r = __shfl_down_sync(0xffffffffu, em, off);
            int   a2r = __shfl_down_sync(0xffffffffu, ea, off);
            es += s2r;
            et += t2r;
            if (m2r > em || (m2r == em && a2r < ea)) ea = a2r;
            em = fmaxf(em, m2r);
        }
        if (tid == 0) {
            float lse = logf(es);
            bool valid = (lab != IGNORE_IDX);
            float per = lse - (1.0f - EPS_SMOOTH) * xl - EPS_SMOOTH * (et / (float)VV);
            g_per_tok[row] = valid ? per : 0.f;
            g_valid[row]   = valid ? 1.f : 0.f;
            g_pred[row]    = ea;
            // release this row's results, then take an arrival ticket
            __threadfence();
            sh_old = atomicAdd(&g_arrive, 1);
        }
    }
    __syncthreads();
    const int old = sh_old;

    if (old < REP_TICKET0) return;       // not one of the last 64 arrivals

    // ---------------- Phase B: rep-loss slice (last 64 arrivals) ----------
    const int sl_id = old - REP_TICKET0; // 0..63
    const int b  = sl_id >> 3;           // batch
    const int sl = sl_id & 7;            // slice within batch
    const int il = tid >> 3;
    const int ch = tid & 7;
    const int i  = sl * ILOC + il;

    // wait for ALL rows (short: only stragglers remain)
    if (tid == 0) {
        while (ld_acquire(&g_arrive) < ROWS) __nanosleep(32);
    }
    __syncthreads();
    __threadfence();

    __shared__ int   sp[SS];
    __shared__ float sv[SS];
    __shared__ float red1[16], red2[16], red3[16], red4[16];

    {
        int r2 = b * SS + tid;
        sp[tid] = g_pred[r2];
        sv[tid] = g_valid[r2];
    }
    __syncthreads();

    float total = sv[tid];
    #pragma unroll
    for (int off = 16; off; off >>= 1) total += __shfl_down_sync(0xffffffffu, total, off);
    if ((tid & 31) == 0) red1[tid >> 5] = total;
    __syncthreads();
    if (tid < 16) {
        float xx = red1[tid];
        #pragma unroll
        for (int off = 8; off; off >>= 1) xx += __shfl_down_sync(0xffffu, xx, off);
        if (tid == 0) red1[0] = xx;
    }
    __syncthreads();
    total = red1[0];
    __syncthreads();

    int   p  = sp[i];
    float vi = sv[i];
    float c = 0.f;
    int lt = 0;
    #pragma unroll 8
    for (int jj = 0; jj < JLEN; jj++) {
        int j = ch + (jj << 3);
        bool match = (sp[j] == p) && (sv[j] > 0.f);
        c += match ? 1.f : 0.f;
        lt |= (match && (j < i)) ? 1 : 0;
    }
    #pragma unroll
    for (int off = 1; off < 8; off <<= 1) {
        c  += __shfl_xor_sync(0xffffffffu, c,  off);
        lt |= __shfl_xor_sync(0xffffffffu, lt, off);
    }

    float ent = 0.f, nu = 0.f, pts = 0.f, vls = 0.f;
    if (ch == 0) {
        bool first = (vi > 0.f) && !lt;
        if (first) {
            float pr = c / fmaxf(total, 1.f);
            ent = -pr * logf(pr + 1e-10f);
            nu  = 1.f;
        }
        int r2 = b * SS + i;
        pts = g_per_tok[r2];
        vls = vi;
    }

    #pragma unroll
    for (int off = 16; off; off >>= 1) {
        ent += __shfl_down_sync(0xffffffffu, ent, off);
        nu  += __shfl_down_sync(0xffffffffu, nu,  off);
        pts += __shfl_down_sync(0xffffffffu, pts, off);
        vls += __shfl_down_sync(0xffffffffu, vls, off);
    }
    if ((tid & 31) == 0) { red1[tid >> 5] = ent; red2[tid >> 5] = nu; red3[tid >> 5] = pts; red4[tid >> 5] = vls; }
    __syncthreads();
    if (tid < 16) {
        float e = red1[tid], n = red2[tid], q = red3[tid], w = red4[tid];
        #pragma unroll
        for (int off = 8; off; off >>= 1) {
            e += __shfl_down_sync(0xffffu, e, off);
            n += __shfl_down_sync(0xffffu, n, off);
            q += __shfl_down_sync(0xffffu, q, off);
            w += __shfl_down_sync(0xffffu, w, off);
        }
        if (tid == 0) {
            g_ent_part[sl_id] = e;
            g_nu_part[sl_id]  = n;
            g_pt_part[sl_id]  = q;
            g_v_part[sl_id]   = w;
            if (sl == 0) g_tot_b[b] = total;
        }
    }
    __syncthreads();

    if (tid == 0) {
        __threadfence();
        int old2 = atomicAdd(&g_arrive2, 1);
        if (old2 == RB_BLOCKS - 1) {
            __threadfence();
            float rep = 0.f;
            #pragma unroll
            for (int bb = 0; bb < BB; bb++) {
                float eb = 0.f, nb = 0.f;
                #pragma unroll
                for (int ss2 = 0; ss2 < SLICES; ss2++) {
                    eb += g_ent_part[bb * SLICES + ss2];
                    nb += g_nu_part[bb * SLICES + ss2];
                }
                float tb2 = g_tot_b[bb];
                rep += (tb2 > 0.f) ? (1.f - eb / logf(nb + 1.f)) : 0.f;
            }
            rep /= (float)BB;
            float cen = 0.f, ced = 0.f;
            #pragma unroll
            for (int jq = 0; jq < RB_BLOCKS; jq++) {
                cen += g_pt_part[jq];
                ced += g_v_part[jq];
            }
            float ce = cen / fmaxf(ced, 1.f);
            float tot = ce + REP_W * rep;
            out[0] = tot;
            if (out_size > 1) out[1] = ce;
            if (out_size > 2) out[2] = rep;
            // replay-safe: all 4096 arrivals and all 64 slice blocks have
            // passed their spins before this point.
            g_arrive  = 0;
            g_arrive2 = 0;
        }
    }
}

extern "C" void kernel_launch(void* const* d_in, const int* in_sizes, int n_in,
                              void* d_out, int out_size) {
    const float* logits = (const float*)d_in[0];
    const void*  labels = d_in[1];

    fused_kernel<<<ROWS, RK_THREADS>>>(logits, labels, (float*)d_out, out_size);
}

// round 15
// speedup vs baseline: 1.3094x; 1.1976x over previous
#include <cuda_runtime.h>
#include <math_constants.h>

// Problem constants (fixed shape)
#define BB 8
#define SS 512
#define ROWS (BB * SS)
#define VV 32000
#define V4 (VV / 4)            // 8000 float4 per row
#define EPS_SMOOTH 0.1f
#define REP_W 0.2f
#define IGNORE_IDX (-100)

#define RK_THREADS 256
#define FULL_IT (V4 / RK_THREADS)       // 31
#define REM (V4 - FULL_IT * RK_THREADS) // 64

#define GRID 592                         // 4 blocks/SM x 148 SMs, all resident
#define NW (RK_THREADS / 32)             // 8 warps
#define SLICES 8
#define RB_BLOCKS (BB * SLICES)          // 64
#define ILOC (SS / SLICES)               // 64
#define JLEN (SS / 4)                    // 128 j per chunk-thread (4 chunks/i)

// Scratch (no allocation allowed -> __device__ globals; zero-init; counters
// reset by the final combine block each replay)
__device__ float g_per_tok[ROWS];
__device__ float g_valid[ROWS];
__device__ int   g_pred[ROWS];
__device__ float g_ent_part[RB_BLOCKS];
__device__ float g_nu_part[RB_BLOCKS];
__device__ float g_pt_part[RB_BLOCKS];
__device__ float g_v_part[RB_BLOCKS];
__device__ float g_tot_b[BB];
__device__ int   g_arrive;
__device__ int   g_arrive2;

// ---------------- packed f32x2 helpers (Blackwell) ----------------
__device__ __forceinline__ unsigned long long pack2(float a, float b) {
    unsigned long long r;
    asm("mov.b64 %0, {%1, %2};" : "=l"(r) : "f"(a), "f"(b));
    return r;
}
__device__ __forceinline__ void unpack2(unsigned long long p, float& a, float& b) {
    asm("mov.b64 {%0, %1}, %2;" : "=f"(a), "=f"(b) : "l"(p));
}
__device__ __forceinline__ unsigned long long addf2(unsigned long long a, unsigned long long b) {
    unsigned long long r;
    asm("add.rn.f32x2 %0, %1, %2;" : "=l"(r) : "l"(a), "l"(b));
    return r;
}
__device__ __forceinline__ unsigned long long mulf2(unsigned long long a, unsigned long long b) {
    unsigned long long r;
    asm("mul.rn.f32x2 %0, %1, %2;" : "=l"(r) : "l"(a), "l"(b));
    return r;
}
__device__ __forceinline__ float ex2f(float x) {
    float r;
    asm("ex2.approx.f32 %0, %1;" : "=f"(r) : "f"(x));
    return r;
}
__device__ __forceinline__ int ld_acquire(int* p) {
    int v;
    asm volatile("ld.global.acquire.gpu.b32 %0, [%1];" : "=r"(v) : "l"(p));
    return v;
}

// ---------------------------------------------------------------------------
// Persistent fused kernel (R8 structure) at 256 threads x 4 blocks/SM:
// same 1024 threads/SM, but 4 independent streams per SM — per-row pipeline
// drains are staggered 4-ways and each reduction stalls only 1/4 of the SM.
// ---------------------------------------------------------------------------
__global__ void __launch_bounds__(RK_THREADS, 4)
fused_kernel(const float* __restrict__ logits, const void* __restrict__ labels,
             float* __restrict__ out, int out_size) {
    const int tid = threadIdx.x;
    const int bid = blockIdx.x;

    __shared__ float shs[2][NW], sht[2][NW], shm[2][NW];
    __shared__ int   sha[2][NW];

    // label width detect: warp 0 only, result in registers
    int is64 = 0;
    if (tid < 32) {
        const int* lw = (const int*)labels;
        bool ok = true;
        #pragma unroll
        for (int kq = 0; kq < 8; kq++) {
            int pi = tid + kq * 32;
            int lo = __ldg(&lw[2 * pi]);
            int hi = __ldg(&lw[2 * pi + 1]);
            if (hi != (lo < 0 ? -1 : 0)) ok = false;
        }
        unsigned ball = __ballot_sync(0xffffffffu, ok);
        is64 = (ball == 0xffffffffu) ? 1 : 0;
    }

    const unsigned long long L2E2 = pack2(1.4426950408889634f, 1.4426950408889634f);

    // ---------------- Phase A: rows ----------------
    int par = 0;
    for (int row = bid; row < ROWS; row += GRID, par ^= 1) {
        const float* __restrict__ x = logits + (size_t)row * VV;
        const float4* __restrict__ x4 = (const float4*)x;

        // prefetch label -> x[label] (resolves during the row stream)
        long long lab = 0;
        float xl = 0.f;
        if (tid == 0) {
            if (is64) lab = ((const long long*)labels)[row];
            else      lab = (long long)(((const int*)labels)[row]);
            int li = (lab != IGNORE_IDX) ? (int)lab : 0;
            xl = __ldg(&x[li]);
        }

        unsigned long long s01 = 0ull, s23 = 0ull;
        unsigned long long t01 = 0ull, t23 = 0ull;
        float k0 = -CUDART_INF_F, k1 = -CUDART_INF_F, k2 = -CUDART_INF_F, k3 = -CUDART_INF_F;

        // 5-bit iteration key in the low mantissa bits (kk up to 31)
        #define BODY(kk, i)                                                         \
            do {                                                                    \
                float4 v = x4[(i)];                                                 \
                unsigned long long vxy = pack2(v.x, v.y);                           \
                unsigned long long vzw = pack2(v.z, v.w);                           \
                t01 = addf2(t01, vxy);                                              \
                t23 = addf2(t23, vzw);                                              \
                unsigned long long wxy = mulf2(vxy, L2E2);                          \
                unsigned long long wzw = mulf2(vzw, L2E2);                          \
                float w0, w1, w2, w3;                                               \
                unpack2(wxy, w0, w1);                                               \
                unpack2(wzw, w2, w3);                                               \
                float e0 = ex2f(w0), e1 = ex2f(w1), e2 = ex2f(w2), e3 = ex2f(w3);   \
                s01 = addf2(s01, pack2(e0, e1));                                    \
                s23 = addf2(s23, pack2(e2, e3));                                    \
                k0 = fmaxf(k0, __int_as_float((__float_as_int(v.x) & ~31) | (kk))); \
                k1 = fmaxf(k1, __int_as_float((__float_as_int(v.y) & ~31) | (kk))); \
                k2 = fmaxf(k2, __int_as_float((__float_as_int(v.z) & ~31) | (kk))); \
                k3 = fmaxf(k3, __int_as_float((__float_as_int(v.w) & ~31) | (kk))); \
            } while (0)

        #pragma unroll 5
        for (int k = 0; k < FULL_IT; k++) {
            BODY(k, tid + k * RK_THREADS);
        }
        if (tid < REM) {
            BODY(FULL_IT, tid + FULL_IT * RK_THREADS);
        }
        #undef BODY

        float sa, sb, sc, sd, ta, tb, tc, td;
        unpack2(s01, sa, sb);
        unpack2(s23, sc, sd);
        unpack2(t01, ta, tb);
        unpack2(t23, tc, td);
        float s = (sa + sb) + (sc + sd);
        float t = (ta + tb) + (tc + td);

        float bk = k0;
        int bs = 0;
        if (k1 > bk) { bk = k1; bs = 1; }
        if (k2 > bk) { bk = k2; bs = 2; }
        if (k3 > bk) { bk = k3; bs = 3; }
        int kb = __float_as_int(bk);
        int iter = kb & 31;
        float m = __int_as_float(kb & ~31);
        int am = (((iter * RK_THREADS) + tid) << 2) + bs;

        #pragma unroll
        for (int off = 16; off; off >>= 1) {
            float s2r = __shfl_down_sync(0xffffffffu, s, off);
            float t2r = __shfl_down_sync(0xffffffffu, t, off);
            float m2r = __shfl_down_sync(0xffffffffu, m, off);
            int   a2r = __shfl_down_sync(0xffffffffu, am, off);
            s += s2r;
            t += t2r;
            if (m2r > m || (m2r == m && a2r < am)) am = a2r;
            m = fmaxf(m, m2r);
        }

        int wid = tid >> 5;
        if ((tid & 31) == 0) { shs[par][wid] = s; sht[par][wid] = t; shm[par][wid] = m; sha[par][wid] = am; }
        __syncthreads();
        // no trailing barrier: next row uses the other parity scratch set

        if (tid < 32) {
            float es = 0.f, et = 0.f, em = -CUDART_INF_F;
            int   ea = 0x7fffffff;
            if (tid < NW) { es = shs[par][tid]; et = sht[par][tid]; em = shm[par][tid]; ea = sha[par][tid]; }
            #pragma unroll
            for (int off = NW / 2; off; off >>= 1) {
                float s2r = __shfl_down_sync(0xffffffffu, es, off);
                float t2r = __shfl_down_sync(0xffffffffu, et, off);
                float m2r = __shfl_down_sync(0xffffffffu, em, off);
                int   a2r = __shfl_down_sync(0xffffffffu, ea, off);
                es += s2r;
                et += t2r;
                if (m2r > em || (m2r == em && a2r < ea)) ea = a2r;
                em = fmaxf(em, m2r);
            }
            if (tid == 0) {
                float lse = logf(es);
                bool valid = (lab != IGNORE_IDX);
                float per = lse - (1.0f - EPS_SMOOTH) * xl - EPS_SMOOTH * (et / (float)VV);
                g_per_tok[row] = valid ? per : 0.f;
                g_valid[row]   = valid ? 1.f : 0.f;
                g_pred[row]    = ea;
            }
        }
    }

    // ---------------- grid barrier ----------------
    __threadfence();
    __syncthreads();
    if (tid == 0) atomicAdd(&g_arrive, 1);

    if (bid >= RB_BLOCKS) return;

    if (tid == 0) {
        while (ld_acquire(&g_arrive) < GRID) __nanosleep(64);
    }
    __syncthreads();
    __threadfence();

    // ---------------- Phase B: rep loss (256 threads/block) ----------------
    const int b  = bid >> 3;        // batch
    const int sl = bid & 7;         // slice
    const int il = tid >> 2;        // i_local 0..63
    const int ch = tid & 3;         // j chunk 0..3
    const int i  = sl * ILOC + il;  // i within batch

    __shared__ int   sp[SS];
    __shared__ float sv[SS];
    __shared__ float red1[NW], red2[NW], red3[NW], red4[NW];

    {
        int r0 = b * SS + tid;
        sp[tid]              = g_pred[r0];
        sv[tid]              = g_valid[r0];
        sp[tid + RK_THREADS] = g_pred[r0 + RK_THREADS];
        sv[tid + RK_THREADS] = g_valid[r0 + RK_THREADS];
    }
    __syncthreads();

    // total valid for batch
    float total = sv[tid] + sv[tid + RK_THREADS];
    #pragma unroll
    for (int off = 16; off; off >>= 1) total += __shfl_down_sync(0xffffffffu, total, off);
    if ((tid & 31) == 0) red1[tid >> 5] = total;
    __syncthreads();
    if (tid < 32) {
        float xx = (tid < NW) ? red1[tid] : 0.f;
        #pragma unroll
        for (int off = NW / 2; off; off >>= 1) xx += __shfl_down_sync(0xffffffffu, xx, off);
        if (tid == 0) red1[0] = xx;
    }
    __syncthreads();
    total = red1[0];
    __syncthreads();

    // per-i count + any-earlier-match; 4 chunk-threads per i, 128 j each
    int   p  = sp[i];
    float vi = sv[i];
    float c = 0.f;
    int lt = 0;
    #pragma unroll 8
    for (int jj = 0; jj < JLEN; jj++) {
        int j = ch + (jj << 2);
        bool match = (sp[j] == p) && (sv[j] > 0.f);
        c += match ? 1.f : 0.f;
        lt |= (match && (j < i)) ? 1 : 0;
    }
    #pragma unroll
    for (int off = 1; off < 4; off <<= 1) {
        c  += __shfl_xor_sync(0xffffffffu, c,  off);
        lt |= __shfl_xor_sync(0xffffffffu, lt, off);
    }

    float ent = 0.f, nu = 0.f, pts = 0.f, vls = 0.f;
    if (ch == 0) {
        bool first = (vi > 0.f) && !lt;
        if (first) {
            float pr = c / fmaxf(total, 1.f);
            ent = -pr * logf(pr + 1e-10f);
            nu  = 1.f;
        }
        int r2 = b * SS + i;
        pts = g_per_tok[r2];
        vls = vi;
    }

    #pragma unroll
    for (int off = 16; off; off >>= 1) {
        ent += __shfl_down_sync(0xffffffffu, ent, off);
        nu  += __shfl_down_sync(0xffffffffu, nu,  off);
        pts += __shfl_down_sync(0xffffffffu, pts, off);
        vls += __shfl_down_sync(0xffffffffu, vls, off);
    }
    if ((tid & 31) == 0) { red1[tid >> 5] = ent; red2[tid >> 5] = nu; red3[tid >> 5] = pts; red4[tid >> 5] = vls; }
    __syncthreads();
    if (tid < 32) {
        float e = (tid < NW) ? red1[tid] : 0.f;
        float n = (tid < NW) ? red2[tid] : 0.f;
        float q = (tid < NW) ? red3[tid] : 0.f;
        float w = (tid < NW) ? red4[tid] : 0.f;
        #pragma unroll
        for (int off = NW / 2; off; off >>= 1) {
            e += __shfl_down_sync(0xffffffffu, e, off);
            n += __shfl_down_sync(0xffffffffu, n, off);
            q += __shfl_down_sync(0xffffffffu, q, off);
            w += __shfl_down_sync(0xffffffffu, w, off);
        }
        if (tid == 0) {
            g_ent_part[bid] = e;
            g_nu_part[bid]  = n;
            g_pt_part[bid]  = q;
            g_v_part[bid]   = w;
            if (sl == 0) g_tot_b[b] = total;
        }
    }
    __syncthreads();

    if (tid == 0) {
        __threadfence();
        int old = atomicAdd(&g_arrive2, 1);
        if (old == RB_BLOCKS - 1) {
            __threadfence();
            float rep = 0.f;
            #pragma unroll
            for (int bb = 0; bb < BB; bb++) {
                float eb = 0.f, nb = 0.f;
                #pragma unroll
                for (int ss2 = 0; ss2 < SLICES; ss2++) {
                    eb += g_ent_part[bb * SLICES + ss2];
                    nb += g_nu_part[bb * SLICES + ss2];
                }
                float tb2 = g_tot_b[bb];
                rep += (tb2 > 0.f) ? (1.f - eb / logf(nb + 1.f)) : 0.f;
            }
            rep /= (float)BB;
            float cen = 0.f, ced = 0.f;
            #pragma unroll
            for (int jq = 0; jq < RB_BLOCKS; jq++) {
                cen += g_pt_part[jq];
                ced += g_v_part[jq];
            }
            float ce = cen / fmaxf(ced, 1.f);
            float tot = ce + REP_W * rep;
            out[0] = tot;
            if (out_size > 1) out[1] = ce;
            if (out_size > 2) out[2] = rep;
            g_arrive  = 0;   // replay-safe resets (all spins already passed)
            g_arrive2 = 0;
        }
    }
}

extern "C" void kernel_launch(void* const* d_in, const int* in_sizes, int n_in,
                              void* d_out, int out_size) {
    const float* logits = (const float*)d_in[0];
    const void*  labels = d_in[1];

    fused_kernel<<<GRID, RK_THREADS>>>(logits, labels, (float*)d_out, out_size);
}